// round 1
// baseline (speedup 1.0000x reference)
#include <cuda_runtime.h>

// ---------------------------------------------------------------------------
// Problem constants (shapes fixed by the dataset)
//   N = 131072 nodes, S = 32 features, E = 2M edges, B = 4096 graphs
// ---------------------------------------------------------------------------
#define MAXN 131072
#define MAXB 4096

// Scratch (static device globals; no runtime allocation)
__device__ float g_wdi[3][512];       // per-conv: (W1[0:F] - W1[F:2F]), [F x 16]
__device__ float g_wdj[3][512];       // per-conv: W1[F:2F], [F x 16]
__device__ float g_awt[256 * 64];     // aW transposed to [256, 64] (f-major)
__device__ float g_hacc[MAXN * 32];   // edge-conv accumulator
__device__ float g_h[MAXN * 32];      // normalized activations / dense input
__device__ float g_stats[64];         // per-channel sum / sumsq
__device__ float g_t1[MAXB * 256];
__device__ float g_t2[MAXB * 256];
__device__ float g_val[MAXB];
__device__ float g_adv[MAXB * 64];

// ---------------------------------------------------------------------------
// prep: fold the EdgeConv concat into two weight matrices, transpose aW
//   hidden = xi @ (W1a - W1b) + xj @ W1b + b1
// ---------------------------------------------------------------------------
__global__ void prep_kernel(const float* __restrict__ c1W1,
                            const float* __restrict__ c2W1,
                            const float* __restrict__ c3W1,
                            const float* __restrict__ aW) {
    int t = blockIdx.x * blockDim.x + threadIdx.x;
    if (t < 32) {
        int k = t >> 4, j = t & 15;
        g_wdi[0][t] = c1W1[k * 16 + j] - c1W1[(2 + k) * 16 + j];
        g_wdj[0][t] = c1W1[(2 + k) * 16 + j];
    }
    if (t < 512) {
        int k = t >> 4, j = t & 15;
        g_wdi[1][t] = c2W1[k * 16 + j] - c2W1[(32 + k) * 16 + j];
        g_wdj[1][t] = c2W1[(32 + k) * 16 + j];
        g_wdi[2][t] = c3W1[k * 16 + j] - c3W1[(32 + k) * 16 + j];
        g_wdj[2][t] = c3W1[(32 + k) * 16 + j];
    }
    for (int i = t; i < 256 * 64; i += blockDim.x * gridDim.x) {
        int f = i >> 6, col = i & 63;                 // col = n*2 + a
        g_awt[i] = aW[(col >> 1) * 512 + f * 2 + (col & 1)];
    }
}

// ---------------------------------------------------------------------------
// EdgeConv: one thread per edge. Messages scatter-added to g_hacc via
// red.global.add.v4.f32. ci selects the prepped weight set.
// ---------------------------------------------------------------------------
template <int F>
__global__ void edge_conv_kernel(const float* __restrict__ xext,
                                 const int* __restrict__ src,
                                 const int* __restrict__ dst, int ci,
                                 const float* __restrict__ b1v,
                                 const float* __restrict__ W2,
                                 const float* __restrict__ b2v, int E) {
    __shared__ float sWI[F * 16];
    __shared__ float sWJ[F * 16];
    __shared__ float sB1[16];
    __shared__ float sW2[16 * 32];
    __shared__ float sB2[32];
    for (int i = threadIdx.x; i < F * 16; i += blockDim.x) {
        sWI[i] = g_wdi[ci][i];
        sWJ[i] = g_wdj[ci][i];
    }
    for (int i = threadIdx.x; i < 16; i += blockDim.x) sB1[i] = b1v[i];
    for (int i = threadIdx.x; i < 512; i += blockDim.x) sW2[i] = W2[i];
    for (int i = threadIdx.x; i < 32; i += blockDim.x) sB2[i] = b2v[i];
    __syncthreads();

    int e = blockIdx.x * blockDim.x + threadIdx.x;
    if (e >= E) return;
    int s = src[e];
    int d = dst[e];

    const float* xp = (F == 2) ? xext : g_h;

    float h[16];
#pragma unroll
    for (int j = 0; j < 16; j++) h[j] = sB1[j];

    // ---- xi @ Wd ----
    {
        float xv[F];
        if (F == 32) {
            const float4* p = reinterpret_cast<const float4*>(xp + (size_t)d * F);
#pragma unroll
            for (int k4 = 0; k4 < F / 4; k4++) {
                float4 v = p[k4];
                xv[k4 * 4 + 0] = v.x; xv[k4 * 4 + 1] = v.y;
                xv[k4 * 4 + 2] = v.z; xv[k4 * 4 + 3] = v.w;
            }
        } else {
            const float2* p = reinterpret_cast<const float2*>(xp + (size_t)d * F);
            float2 v = p[0];
            xv[0] = v.x; xv[1] = v.y;
        }
#pragma unroll
        for (int k = 0; k < F; k++) {
            float v = xv[k];
#pragma unroll
            for (int j = 0; j < 16; j++) h[j] = fmaf(v, sWI[k * 16 + j], h[j]);
        }
    }
    // ---- xj @ Wb ----
    {
        float xv[F];
        if (F == 32) {
            const float4* p = reinterpret_cast<const float4*>(xp + (size_t)s * F);
#pragma unroll
            for (int k4 = 0; k4 < F / 4; k4++) {
                float4 v = p[k4];
                xv[k4 * 4 + 0] = v.x; xv[k4 * 4 + 1] = v.y;
                xv[k4 * 4 + 2] = v.z; xv[k4 * 4 + 3] = v.w;
            }
        } else {
            const float2* p = reinterpret_cast<const float2*>(xp + (size_t)s * F);
            float2 v = p[0];
            xv[0] = v.x; xv[1] = v.y;
        }
#pragma unroll
        for (int k = 0; k < F; k++) {
            float v = xv[k];
#pragma unroll
            for (int j = 0; j < 16; j++) h[j] = fmaf(v, sWJ[k * 16 + j], h[j]);
        }
    }

#pragma unroll
    for (int j = 0; j < 16; j++) h[j] = fmaxf(h[j], 0.0f);

    float o[32];
#pragma unroll
    for (int j = 0; j < 32; j++) o[j] = sB2[j];
#pragma unroll
    for (int i = 0; i < 16; i++) {
        float hv = h[i];
#pragma unroll
        for (int j = 0; j < 32; j++) o[j] = fmaf(hv, sW2[i * 32 + j], o[j]);
    }

    float* a = g_hacc + (size_t)d * 32;
#pragma unroll
    for (int j4 = 0; j4 < 8; j4++) {
        asm volatile("red.global.add.v4.f32 [%0], {%1, %2, %3, %4};" ::
                         "l"(a + j4 * 4),
                     "f"(o[j4 * 4 + 0]), "f"(o[j4 * 4 + 1]),
                     "f"(o[j4 * 4 + 2]), "f"(o[j4 * 4 + 3])
                     : "memory");
    }
}

// ---------------------------------------------------------------------------
// BN stats: per-channel sum / sumsq over all N rows (lane == channel)
// ---------------------------------------------------------------------------
__global__ void bn_stats_kernel(int N) {
    int lane = threadIdx.x & 31;
    int warp = threadIdx.x >> 5;
    const int nwarp = 8;  // blockDim 256
    float s = 0.0f, ss = 0.0f;
    for (int r = blockIdx.x * nwarp + warp; r < N; r += gridDim.x * nwarp) {
        float v = g_hacc[(size_t)r * 32 + lane];
        s += v;
        ss += v * v;
    }
    __shared__ float sh[2][8][32];
    sh[0][warp][lane] = s;
    sh[1][warp][lane] = ss;
    __syncthreads();
    if (warp == 0) {
        float a = 0.0f, b = 0.0f;
#pragma unroll
        for (int w = 0; w < nwarp; w++) {
            a += sh[0][w][lane];
            b += sh[1][w][lane];
        }
        atomicAdd(&g_stats[lane], a);
        atomicAdd(&g_stats[32 + lane], b);
    }
}

// ---------------------------------------------------------------------------
// BN apply (+ReLU): g_h = relu((g_hacc - mu) * rsqrt(var+eps) * g + b)
// ---------------------------------------------------------------------------
__global__ void bn_apply_kernel(const float* __restrict__ gamma,
                                const float* __restrict__ beta, int N) {
    __shared__ float scale[32], shift[32];
    if (threadIdx.x < 32) {
        int c = threadIdx.x;
        float invn = 1.0f / (float)N;
        float mu = g_stats[c] * invn;
        float var = g_stats[32 + c] * invn - mu * mu;
        float sc = rsqrtf(var + 1e-5f) * gamma[c];
        scale[c] = sc;
        shift[c] = beta[c] - mu * sc;
    }
    __syncthreads();
    int total = N * 32;
    for (int i = blockIdx.x * blockDim.x + threadIdx.x; i < total;
         i += gridDim.x * blockDim.x) {
        int c = i & 31;
        g_h[i] = fmaxf(fmaf(g_hacc[i], scale[c], shift[c]), 0.0f);
    }
}

// ---------------------------------------------------------------------------
// Tiled fp32 GEMM: C[M,N] = act(A[M,K] @ B[K,N] + bias)
// 64x64 block tile, BK=16, 256 threads, 4x4 micro-tile per thread
// ---------------------------------------------------------------------------
template <bool RELU>
__global__ void gemm_bias_kernel(const float* __restrict__ A,
                                 const float* __restrict__ Bm,
                                 const float* __restrict__ bias,
                                 float* __restrict__ C, int M, int N, int K) {
    const int BM = 64, BN = 64, BK = 16;
    __shared__ float As[BK][BM + 1];
    __shared__ float Bs[BK][BN];
    int tx = threadIdx.x & 15;
    int ty = threadIdx.x >> 4;
    int bm = blockIdx.y * BM;
    int bn = blockIdx.x * BN;

    float acc[4][4];
#pragma unroll
    for (int u = 0; u < 4; u++)
#pragma unroll
        for (int v = 0; v < 4; v++) acc[u][v] = 0.0f;

    for (int k0 = 0; k0 < K; k0 += BK) {
        for (int i = threadIdx.x; i < BM * BK; i += 256) {
            int r = i / BK, c = i % BK;
            As[c][r] = A[(size_t)(bm + r) * K + k0 + c];
        }
        for (int i = threadIdx.x; i < BK * BN; i += 256) {
            int r = i / BN, c = i % BN;
            Bs[r][c] = Bm[(size_t)(k0 + r) * N + bn + c];
        }
        __syncthreads();
#pragma unroll
        for (int k = 0; k < BK; k++) {
            float a[4], b[4];
#pragma unroll
            for (int u = 0; u < 4; u++) a[u] = As[k][ty * 4 + u];
            float4 bv = *reinterpret_cast<const float4*>(&Bs[k][tx * 4]);
            b[0] = bv.x; b[1] = bv.y; b[2] = bv.z; b[3] = bv.w;
#pragma unroll
            for (int u = 0; u < 4; u++)
#pragma unroll
                for (int v = 0; v < 4; v++) acc[u][v] = fmaf(a[u], b[v], acc[u][v]);
        }
        __syncthreads();
    }
#pragma unroll
    for (int u = 0; u < 4; u++) {
        int row = bm + ty * 4 + u;
#pragma unroll
        for (int v = 0; v < 4; v++) {
            int col = bn + tx * 4 + v;
            float r = acc[u][v] + bias[col];
            if (RELU) r = fmaxf(r, 0.0f);
            C[(size_t)row * N + col] = r;
        }
    }
}

// ---------------------------------------------------------------------------
// value head: val[b] = dot(X[b,:256], vW) + vb  (one warp per row)
// ---------------------------------------------------------------------------
__global__ void value_kernel(const float* __restrict__ X,
                             const float* __restrict__ vW,
                             const float* __restrict__ vb, int B) {
    int gwarp = (blockIdx.x * blockDim.x + threadIdx.x) >> 5;
    int lane = threadIdx.x & 31;
    int nwarps = (gridDim.x * blockDim.x) >> 5;
    for (int b = gwarp; b < B; b += nwarps) {
        const float* row = X + (size_t)b * 256;
        float s = 0.0f;
#pragma unroll
        for (int f = lane; f < 256; f += 32) s = fmaf(row[f], vW[f], s);
#pragma unroll
        for (int o = 16; o; o >>= 1) s += __shfl_xor_sync(0xffffffffu, s, o);
        if (lane == 0) g_val[b] = s + vb[0];
    }
}

// ---------------------------------------------------------------------------
// q = v + adv - mean_a(adv)  (A=2: q = v + (adv - adv_pair)/2)
// ---------------------------------------------------------------------------
__global__ void q_kernel(float* __restrict__ q, int B) {
    int i = blockIdx.x * blockDim.x + threadIdx.x;
    if (i >= B * 64) return;
    int b = i >> 6;
    float a0 = g_adv[i];
    float a1 = g_adv[i ^ 1];
    q[i] = g_val[b] + 0.5f * (a0 - a1);
}

// ---------------------------------------------------------------------------
extern "C" void kernel_launch(void* const* d_in, const int* in_sizes, int n_in,
                              void* d_out, int out_size) {
    const float* x    = (const float*)d_in[0];
    const int*   ei   = (const int*)d_in[1];
    const float* c1W1 = (const float*)d_in[2];
    const float* c1b1 = (const float*)d_in[3];
    const float* c1W2 = (const float*)d_in[4];
    const float* c1b2 = (const float*)d_in[5];
    const float* c2W1 = (const float*)d_in[6];
    const float* c2b1 = (const float*)d_in[7];
    const float* c2W2 = (const float*)d_in[8];
    const float* c2b2 = (const float*)d_in[9];
    const float* c3W1 = (const float*)d_in[10];
    const float* c3b1 = (const float*)d_in[11];
    const float* c3W2 = (const float*)d_in[12];
    const float* c3b2 = (const float*)d_in[13];
    const float* bn_g = (const float*)d_in[14];
    const float* bn_b = (const float*)d_in[15];
    const float* mW1  = (const float*)d_in[16];
    const float* mb1  = (const float*)d_in[17];
    const float* mW2  = (const float*)d_in[18];
    const float* mb2  = (const float*)d_in[19];
    const float* mW3  = (const float*)d_in[20];
    const float* mb3  = (const float*)d_in[21];
    const float* vW   = (const float*)d_in[22];
    const float* vb   = (const float*)d_in[23];
    const float* aW   = (const float*)d_in[24];
    const float* ab   = (const float*)d_in[25];

    int N = in_sizes[0] / 2;
    int E = in_sizes[1] / 2;
    int B = N / 32;
    const int* src = ei;
    const int* dstp = ei + E;

    float *hacc, *h, *stats, *t1, *t2, *adv, *awt;
    cudaGetSymbolAddress((void**)&hacc, g_hacc);
    cudaGetSymbolAddress((void**)&h, g_h);
    cudaGetSymbolAddress((void**)&stats, g_stats);
    cudaGetSymbolAddress((void**)&t1, g_t1);
    cudaGetSymbolAddress((void**)&t2, g_t2);
    cudaGetSymbolAddress((void**)&adv, g_adv);
    cudaGetSymbolAddress((void**)&awt, g_awt);

    prep_kernel<<<64, 256>>>(c1W1, c2W1, c3W1, aW);

    const int TPB = 256;
    int eblocks = (E + TPB - 1) / TPB;
    size_t hbytes = (size_t)N * 32 * sizeof(float);

    // ---- conv1 + BN1 ----
    cudaMemsetAsync(hacc, 0, hbytes, 0);
    cudaMemsetAsync(stats, 0, 64 * sizeof(float), 0);
    edge_conv_kernel<2><<<eblocks, TPB>>>(x, src, dstp, 0, c1b1, c1W2, c1b2, E);
    bn_stats_kernel<<<512, 256>>>(N);
    bn_apply_kernel<<<512, 256>>>(bn_g + 0, bn_b + 0, N);

    // ---- conv2 + BN2 ----
    cudaMemsetAsync(hacc, 0, hbytes, 0);
    cudaMemsetAsync(stats, 0, 64 * sizeof(float), 0);
    edge_conv_kernel<32><<<eblocks, TPB>>>(x, src, dstp, 1, c2b1, c2W2, c2b2, E);
    bn_stats_kernel<<<512, 256>>>(N);
    bn_apply_kernel<<<512, 256>>>(bn_g + 32, bn_b + 32, N);

    // ---- conv3 + BN3 ----
    cudaMemsetAsync(hacc, 0, hbytes, 0);
    cudaMemsetAsync(stats, 0, 64 * sizeof(float), 0);
    edge_conv_kernel<32><<<eblocks, TPB>>>(x, src, dstp, 2, c3b1, c3W2, c3b2, E);
    bn_stats_kernel<<<512, 256>>>(N);
    bn_apply_kernel<<<512, 256>>>(bn_g + 64, bn_b + 64, N);

    // ---- dense head: g_h is [B, 1024] row-major by construction ----
    dim3 g1(256 / 64, B / 64);
    gemm_bias_kernel<true><<<g1, 256>>>(h, mW1, mb1, t1, B, 256, 1024);
    gemm_bias_kernel<true><<<g1, 256>>>(t1, mW2, mb2, t2, B, 256, 256);
    gemm_bias_kernel<true><<<g1, 256>>>(t2, mW3, mb3, t1, B, 256, 256);

    value_kernel<<<64, 256>>>(t1, vW, vb, B);
    dim3 g2(1, B / 64);
    gemm_bias_kernel<false><<<g2, 256>>>(t1, awt, ab, adv, B, 64, 256);
    q_kernel<<<(B * 64 + 255) / 256, 256>>>((float*)d_out, B);
}

// round 2
// speedup vs baseline: 1.5017x; 1.5017x over previous
#include <cuda_runtime.h>

// ---------------------------------------------------------------------------
// Shapes fixed by the dataset: N=131072 nodes, S=32, E=2M edges, B=4096
// ---------------------------------------------------------------------------
#define MAXN 131072
#define MAXB 4096

// Scratch (static device globals)
__device__ float g_wdi[3][512];       // per-conv: (W1a - W1b), [F x 16]
__device__ float g_wdj[3][512];       // per-conv: W1b,         [F x 16]
__device__ float g_awt[256 * 64];     // aW transposed to [256, 64]
__device__ float g_pij[MAXN * 32];    // per-node [pi(16) | pj(16)]
__device__ float g_h16[MAXN * 16];    // aggregated relu(hidden) per node
__device__ float g_hacc[MAXN * 32];   // conv output (pre-BN)
__device__ float g_h[MAXN * 32];      // final activations (dense input)
__device__ int   g_deg[MAXN];         // in-degree per node
__device__ float g_stats[64];         // per-channel sum / sumsq
__device__ float g_t1[MAXB * 256];
__device__ float g_t2[MAXB * 256];
__device__ float g_val[MAXB];
__device__ float g_adv[MAXB * 64];

// ---------------------------------------------------------------------------
// prep: fold EdgeConv concat into two weight mats; transpose aW
// ---------------------------------------------------------------------------
__global__ void prep_kernel(const float* __restrict__ c1W1,
                            const float* __restrict__ c2W1,
                            const float* __restrict__ c3W1,
                            const float* __restrict__ aW) {
    int t = blockIdx.x * blockDim.x + threadIdx.x;
    if (t < 32) {
        int k = t >> 4, j = t & 15;
        g_wdi[0][t] = c1W1[k * 16 + j] - c1W1[(2 + k) * 16 + j];
        g_wdj[0][t] = c1W1[(2 + k) * 16 + j];
    }
    if (t < 512) {
        int k = t >> 4, j = t & 15;
        g_wdi[1][t] = c2W1[k * 16 + j] - c2W1[(32 + k) * 16 + j];
        g_wdj[1][t] = c2W1[(32 + k) * 16 + j];
        g_wdi[2][t] = c3W1[k * 16 + j] - c3W1[(32 + k) * 16 + j];
        g_wdj[2][t] = c3W1[(32 + k) * 16 + j];
    }
    for (int i = t; i < 256 * 64; i += blockDim.x * gridDim.x) {
        int f = i >> 6, col = i & 63;
        g_awt[i] = aW[(col >> 1) * 512 + f * 2 + (col & 1)];
    }
}

// in-degree per node (one pass, reused by all 3 convs)
__global__ void deg_kernel(const int* __restrict__ dst, int E) {
    int e = blockIdx.x * blockDim.x + threadIdx.x;
    if (e < E) atomicAdd(&g_deg[dst[e]], 1);
}

// conv1 pi/pj from raw x (F=2)
__global__ void prep1_kernel(const float* __restrict__ x, int N) {
    __shared__ float sWd[32], sWb[32];
    if (threadIdx.x < 32) {
        sWd[threadIdx.x] = g_wdi[0][threadIdx.x];
        sWb[threadIdx.x] = g_wdj[0][threadIdx.x];
    }
    __syncthreads();
    int n = blockIdx.x * blockDim.x + threadIdx.x;
    if (n >= N) return;
    float2 xv = reinterpret_cast<const float2*>(x)[n];
    float out[32];
#pragma unroll
    for (int j = 0; j < 16; j++) {
        out[j]      = fmaf(xv.x, sWd[j], xv.y * sWd[16 + j]);
        out[16 + j] = fmaf(xv.x, sWb[j], xv.y * sWb[16 + j]);
    }
    float4* o = reinterpret_cast<float4*>(g_pij + (size_t)n * 32);
#pragma unroll
    for (int q = 0; q < 8; q++)
        o[q] = make_float4(out[q * 4], out[q * 4 + 1], out[q * 4 + 2], out[q * 4 + 3]);
}

// ---------------------------------------------------------------------------
// edge scatter: h16 = relu(pi[dst] + pj[src] + b1), red.add into g_h16[dst]
// ---------------------------------------------------------------------------
__global__ void edge_scatter_kernel(const int* __restrict__ src,
                                    const int* __restrict__ dst,
                                    const float* __restrict__ b1v, int E) {
    __shared__ float sB1[16];
    if (threadIdx.x < 16) sB1[threadIdx.x] = b1v[threadIdx.x];
    __syncthreads();
    int e = blockIdx.x * blockDim.x + threadIdx.x;
    if (e >= E) return;
    int s = src[e];
    int d = dst[e];
    const float4* pd = reinterpret_cast<const float4*>(g_pij + (size_t)d * 32);
    const float4* ps = reinterpret_cast<const float4*>(g_pij + (size_t)s * 32 + 16);
    float* a = g_h16 + (size_t)d * 16;
#pragma unroll
    for (int q = 0; q < 4; q++) {
        float4 u = pd[q];
        float4 v = ps[q];
        float h0 = fmaxf(u.x + v.x + sB1[q * 4 + 0], 0.0f);
        float h1 = fmaxf(u.y + v.y + sB1[q * 4 + 1], 0.0f);
        float h2 = fmaxf(u.z + v.z + sB1[q * 4 + 2], 0.0f);
        float h3 = fmaxf(u.w + v.w + sB1[q * 4 + 3], 0.0f);
        asm volatile("red.global.add.v4.f32 [%0], {%1, %2, %3, %4};" ::
                         "l"(a + q * 4), "f"(h0), "f"(h1), "f"(h2), "f"(h3)
                     : "memory");
    }
}

// ---------------------------------------------------------------------------
// node post: o = H16agg @ W2 + deg*b2; write g_hacc; fused BN stats
// Launch with grid*block == N exactly (N multiple of 256).
// ---------------------------------------------------------------------------
__global__ void node_post_kernel(const float* __restrict__ W2,
                                 const float* __restrict__ b2v, int N) {
    __shared__ float sW2[512];
    __shared__ float sB2[32];
    __shared__ float ssum[8][32];
    __shared__ float ssq[8][32];
    for (int i = threadIdx.x; i < 512; i += blockDim.x) sW2[i] = W2[i];
    if (threadIdx.x < 32) sB2[threadIdx.x] = b2v[threadIdx.x];
    __syncthreads();

    int n = blockIdx.x * blockDim.x + threadIdx.x;
    int lane = threadIdx.x & 31;
    int warp = threadIdx.x >> 5;

    float hv[16];
    const float4* hp = reinterpret_cast<const float4*>(g_h16 + (size_t)n * 16);
#pragma unroll
    for (int q = 0; q < 4; q++) {
        float4 v = hp[q];
        hv[q * 4 + 0] = v.x; hv[q * 4 + 1] = v.y;
        hv[q * 4 + 2] = v.z; hv[q * 4 + 3] = v.w;
    }
    float dg = (float)g_deg[n];
    float o[32];
#pragma unroll
    for (int j = 0; j < 32; j++) o[j] = dg * sB2[j];
#pragma unroll
    for (int k = 0; k < 16; k++) {
        float v = hv[k];
#pragma unroll
        for (int j = 0; j < 32; j++) o[j] = fmaf(v, sW2[k * 32 + j], o[j]);
    }
    float4* op = reinterpret_cast<float4*>(g_hacc + (size_t)n * 32);
#pragma unroll
    for (int q = 0; q < 8; q++)
        op[q] = make_float4(o[q * 4], o[q * 4 + 1], o[q * 4 + 2], o[q * 4 + 3]);

    // fused BN stats: warp butterfly per channel, then block + global reduce
#pragma unroll
    for (int j = 0; j < 32; j++) {
        float v = o[j];
        float v2 = v * v;
#pragma unroll
        for (int off = 16; off; off >>= 1) {
            v += __shfl_xor_sync(0xffffffffu, v, off);
            v2 += __shfl_xor_sync(0xffffffffu, v2, off);
        }
        if (lane == 0) { ssum[warp][j] = v; ssq[warp][j] = v2; }
    }
    __syncthreads();
    if (warp == 0) {
        float a = 0.0f, b = 0.0f;
#pragma unroll
        for (int w = 0; w < 8; w++) { a += ssum[w][lane]; b += ssq[w][lane]; }
        atomicAdd(&g_stats[lane], a);
        atomicAdd(&g_stats[32 + lane], b);
    }
}

// ---------------------------------------------------------------------------
// BN apply + ReLU, fused with next conv's pi/pj precompute (or final write)
// ---------------------------------------------------------------------------
template <bool FINAL>
__global__ void bn_prep_kernel(const float* __restrict__ gamma,
                               const float* __restrict__ beta, int wi, int N) {
    __shared__ float sc[32], sh[32];
    __shared__ float sWd[512], sWb[512];
    if (threadIdx.x < 32) {
        int c = threadIdx.x;
        float invn = 1.0f / (float)N;
        float mu = g_stats[c] * invn;
        float var = g_stats[32 + c] * invn - mu * mu;
        float s = rsqrtf(var + 1e-5f) * gamma[c];
        sc[c] = s;
        sh[c] = beta[c] - mu * s;
    }
    if (!FINAL) {
        for (int i = threadIdx.x; i < 512; i += blockDim.x) {
            sWd[i] = g_wdi[wi][i];
            sWb[i] = g_wdj[wi][i];
        }
    }
    __syncthreads();
    int n = blockIdx.x * blockDim.x + threadIdx.x;
    if (n >= N) return;

    float hn[32];
    const float4* ip = reinterpret_cast<const float4*>(g_hacc + (size_t)n * 32);
#pragma unroll
    for (int q = 0; q < 8; q++) {
        float4 v = ip[q];
        hn[q * 4 + 0] = fmaxf(fmaf(v.x, sc[q * 4 + 0], sh[q * 4 + 0]), 0.0f);
        hn[q * 4 + 1] = fmaxf(fmaf(v.y, sc[q * 4 + 1], sh[q * 4 + 1]), 0.0f);
        hn[q * 4 + 2] = fmaxf(fmaf(v.z, sc[q * 4 + 2], sh[q * 4 + 2]), 0.0f);
        hn[q * 4 + 3] = fmaxf(fmaf(v.w, sc[q * 4 + 3], sh[q * 4 + 3]), 0.0f);
    }
    if (FINAL) {
        float4* op = reinterpret_cast<float4*>(g_h + (size_t)n * 32);
#pragma unroll
        for (int q = 0; q < 8; q++)
            op[q] = make_float4(hn[q * 4], hn[q * 4 + 1], hn[q * 4 + 2], hn[q * 4 + 3]);
    } else {
        float pi[16], pj[16];
#pragma unroll
        for (int j = 0; j < 16; j++) { pi[j] = 0.0f; pj[j] = 0.0f; }
#pragma unroll
        for (int k = 0; k < 32; k++) {
            float v = hn[k];
#pragma unroll
            for (int j = 0; j < 16; j++) {
                pi[j] = fmaf(v, sWd[k * 16 + j], pi[j]);
                pj[j] = fmaf(v, sWb[k * 16 + j], pj[j]);
            }
        }
        float4* op = reinterpret_cast<float4*>(g_pij + (size_t)n * 32);
#pragma unroll
        for (int q = 0; q < 4; q++) {
            op[q] = make_float4(pi[q * 4], pi[q * 4 + 1], pi[q * 4 + 2], pi[q * 4 + 3]);
            op[4 + q] = make_float4(pj[q * 4], pj[q * 4 + 1], pj[q * 4 + 2], pj[q * 4 + 3]);
        }
    }
}

// ---------------------------------------------------------------------------
// Tiled fp32 GEMM: C[M,N] = act(A @ B + bias), 64x64 tile, BK=16
// ---------------------------------------------------------------------------
template <bool RELU>
__global__ void gemm_bias_kernel(const float* __restrict__ A,
                                 const float* __restrict__ Bm,
                                 const float* __restrict__ bias,
                                 float* __restrict__ C, int M, int N, int K) {
    const int BM = 64, BN = 64, BK = 16;
    __shared__ float As[BK][BM + 1];
    __shared__ float Bs[BK][BN];
    int tx = threadIdx.x & 15;
    int ty = threadIdx.x >> 4;
    int bm = blockIdx.y * BM;
    int bn = blockIdx.x * BN;

    float acc[4][4];
#pragma unroll
    for (int u = 0; u < 4; u++)
#pragma unroll
        for (int v = 0; v < 4; v++) acc[u][v] = 0.0f;

    for (int k0 = 0; k0 < K; k0 += BK) {
        for (int i = threadIdx.x; i < BM * BK; i += 256) {
            int r = i / BK, c = i % BK;
            As[c][r] = A[(size_t)(bm + r) * K + k0 + c];
        }
        for (int i = threadIdx.x; i < BK * BN; i += 256) {
            int r = i / BN, c = i % BN;
            Bs[r][c] = Bm[(size_t)(k0 + r) * N + bn + c];
        }
        __syncthreads();
#pragma unroll
        for (int k = 0; k < BK; k++) {
            float a[4], b[4];
#pragma unroll
            for (int u = 0; u < 4; u++) a[u] = As[k][ty * 4 + u];
            float4 bv = *reinterpret_cast<const float4*>(&Bs[k][tx * 4]);
            b[0] = bv.x; b[1] = bv.y; b[2] = bv.z; b[3] = bv.w;
#pragma unroll
            for (int u = 0; u < 4; u++)
#pragma unroll
                for (int v = 0; v < 4; v++) acc[u][v] = fmaf(a[u], b[v], acc[u][v]);
        }
        __syncthreads();
    }
#pragma unroll
    for (int u = 0; u < 4; u++) {
        int row = bm + ty * 4 + u;
#pragma unroll
        for (int v = 0; v < 4; v++) {
            int col = bn + tx * 4 + v;
            float r = acc[u][v] + bias[col];
            if (RELU) r = fmaxf(r, 0.0f);
            C[(size_t)row * N + col] = r;
        }
    }
}

__global__ void value_kernel(const float* __restrict__ X,
                             const float* __restrict__ vW,
                             const float* __restrict__ vb, int B) {
    int gwarp = (blockIdx.x * blockDim.x + threadIdx.x) >> 5;
    int lane = threadIdx.x & 31;
    int nwarps = (gridDim.x * blockDim.x) >> 5;
    for (int b = gwarp; b < B; b += nwarps) {
        const float* row = X + (size_t)b * 256;
        float s = 0.0f;
#pragma unroll
        for (int f = lane; f < 256; f += 32) s = fmaf(row[f], vW[f], s);
#pragma unroll
        for (int o = 16; o; o >>= 1) s += __shfl_xor_sync(0xffffffffu, s, o);
        if (lane == 0) g_val[b] = s + vb[0];
    }
}

__global__ void q_kernel(float* __restrict__ q, int B) {
    int i = blockIdx.x * blockDim.x + threadIdx.x;
    if (i >= B * 64) return;
    int b = i >> 6;
    float a0 = g_adv[i];
    float a1 = g_adv[i ^ 1];
    q[i] = g_val[b] + 0.5f * (a0 - a1);
}

// ---------------------------------------------------------------------------
extern "C" void kernel_launch(void* const* d_in, const int* in_sizes, int n_in,
                              void* d_out, int out_size) {
    const float* x    = (const float*)d_in[0];
    const int*   ei   = (const int*)d_in[1];
    const float* c1W1 = (const float*)d_in[2];
    const float* c1b1 = (const float*)d_in[3];
    const float* c1W2 = (const float*)d_in[4];
    const float* c1b2 = (const float*)d_in[5];
    const float* c2W1 = (const float*)d_in[6];
    const float* c2b1 = (const float*)d_in[7];
    const float* c2W2 = (const float*)d_in[8];
    const float* c2b2 = (const float*)d_in[9];
    const float* c3W1 = (const float*)d_in[10];
    const float* c3b1 = (const float*)d_in[11];
    const float* c3W2 = (const float*)d_in[12];
    const float* c3b2 = (const float*)d_in[13];
    const float* bn_g = (const float*)d_in[14];
    const float* bn_b = (const float*)d_in[15];
    const float* mW1  = (const float*)d_in[16];
    const float* mb1  = (const float*)d_in[17];
    const float* mW2  = (const float*)d_in[18];
    const float* mb2  = (const float*)d_in[19];
    const float* mW3  = (const float*)d_in[20];
    const float* mb3  = (const float*)d_in[21];
    const float* vW   = (const float*)d_in[22];
    const float* vb   = (const float*)d_in[23];
    const float* aW   = (const float*)d_in[24];
    const float* ab   = (const float*)d_in[25];

    int N = in_sizes[0] / 2;
    int E = in_sizes[1] / 2;
    int B = N / 32;
    const int* src = ei;
    const int* dstp = ei + E;

    float *h16, *h, *stats, *t1, *t2, *adv, *awt;
    int* deg;
    cudaGetSymbolAddress((void**)&h16, g_h16);
    cudaGetSymbolAddress((void**)&h, g_h);
    cudaGetSymbolAddress((void**)&stats, g_stats);
    cudaGetSymbolAddress((void**)&t1, g_t1);
    cudaGetSymbolAddress((void**)&t2, g_t2);
    cudaGetSymbolAddress((void**)&adv, g_adv);
    cudaGetSymbolAddress((void**)&awt, g_awt);
    cudaGetSymbolAddress((void**)&deg, g_deg);

    const int TPB = 256;
    int nblocks = N / TPB;              // N is a multiple of 256
    int eblocks = (E + TPB - 1) / TPB;
    size_t h16bytes = (size_t)N * 16 * sizeof(float);

    prep_kernel<<<64, 256>>>(c1W1, c2W1, c3W1, aW);
    cudaMemsetAsync(deg, 0, (size_t)N * sizeof(int), 0);
    deg_kernel<<<eblocks, TPB>>>(dstp, E);
    prep1_kernel<<<nblocks, TPB>>>(x, N);

    const float* b1s[3] = {c1b1, c2b1, c3b1};
    const float* W2s[3] = {c1W2, c2W2, c3W2};
    const float* b2s[3] = {c1b2, c2b2, c3b2};

    for (int c = 0; c < 3; c++) {
        cudaMemsetAsync(h16, 0, h16bytes, 0);
        cudaMemsetAsync(stats, 0, 64 * sizeof(float), 0);
        edge_scatter_kernel<<<eblocks, TPB>>>(src, dstp, b1s[c], E);
        node_post_kernel<<<nblocks, TPB>>>(W2s[c], b2s[c], N);
        if (c < 2)
            bn_prep_kernel<false><<<nblocks, TPB>>>(bn_g + c * 32, bn_b + c * 32,
                                                    c + 1, N);
        else
            bn_prep_kernel<true><<<nblocks, TPB>>>(bn_g + 64, bn_b + 64, 0, N);
    }

    // ---- dense head: g_h is [B, 1024] row-major ----
    dim3 g1(256 / 64, B / 64);
    gemm_bias_kernel<true><<<g1, 256>>>(h, mW1, mb1, t1, B, 256, 1024);
    gemm_bias_kernel<true><<<g1, 256>>>(t1, mW2, mb2, t2, B, 256, 256);
    gemm_bias_kernel<true><<<g1, 256>>>(t2, mW3, mb3, t1, B, 256, 256);

    value_kernel<<<64, 256>>>(t1, vW, vb, B);
    dim3 g2(1, B / 64);
    gemm_bias_kernel<false><<<g2, 256>>>(t1, awt, ab, adv, B, 64, 256);
    q_kernel<<<(B * 64 + 255) / 256, 256>>>((float*)d_out, B);
}